// round 14
// baseline (speedup 1.0000x reference)
#include <cuda_runtime.h>
#include <math.h>

#define DDIM  768
#define SLEN  512
#define NROWS 32768
#define EPSV  1e-8f

#define NBLK    1024             // x 128 thr, 32 rows/block
#define NSTAGES 8                // 32 rows / 4 warps
#define ROW_F4  (DDIM / 4)       // 192 float4 per row
#define NREP    8                // accumulator replicas (contention divider)

// ---- scratch (zero-initialized at load; last block restores zeros) ----
__device__ __align__(16) float g_p8[NREP][DDIM];   // proto partials
__device__ __align__(16) float g_q8[NREP][DDIM];   // q partials
__device__ int      g_entCount;
__device__ int      g_nzCount;
__device__ unsigned g_tk;                          // completion ticket

__device__ __forceinline__ int load_label(const void* __restrict__ labels,
                                          int r, bool isI64) {
    return isI64 ? (int)((const long long*)labels)[r]
                 : ((const int*)labels)[r];
}

__device__ __forceinline__ void cp16(float4* smem_dst, const float4* gsrc) {
    unsigned sa = (unsigned)__cvta_generic_to_shared(smem_dst);
    asm volatile("cp.async.cg.shared.global [%0], [%1], 16;\n"
                 :: "r"(sa), "l"(gsrc));
}
__device__ __forceinline__ void cp_commit() {
    asm volatile("cp.async.commit_group;\n" ::: "memory");
}
template <int N>
__device__ __forceinline__ void cp_wait() {
    asm volatile("cp.async.wait_group %0;\n" :: "n"(N) : "memory");
}

// ---------------------------------------------------------------------------
// ONE kernel. Algebra: loss = dot(q, proto) / (||proto|| * num_tok), with
//   q        = sum over rows with label!=0 of row/||row||      (no proto dep)
//   protoSum = sum over rows with label==entity && s!=0 of row
// Single 90MB pass; R10's barrier-free per-warp cp.async double buffer
// (warp w loads AND consumes row stage*4+w; each lane reads back exactly the
// bytes it copied). q accumulates in warp-PRIVATE smem (plain LDS/STS, no
// atomics, no register growth). protoSum via rare smem atomics (entity rows).
// Per-block partials flush to NREP replicated global arrays (contention
// NBLK/NREP=128 per address). Last block (ticket) computes the loss inline
// and re-zeros all device state for the next graph replay.
// ---------------------------------------------------------------------------
__global__ __launch_bounds__(128) void k_all(const float* __restrict__ logits,
                                             const void*  __restrict__ labels,
                                             const int*   __restrict__ entity_ptr,
                                             float* __restrict__ d_out) {
    __shared__ __align__(16) float4 s_buf[4][2][ROW_F4];   // pipeline, 24KB
    __shared__ __align__(16) float4 s_q[4][ROW_F4];        // warp q acc, 12KB
    __shared__ float s_pacc[DDIM];                         // proto acc, 3KB
    __shared__ int   s_flag;
    __shared__ int   s_nz[4];
    __shared__ int   s_ent[4];
    __shared__ bool  s_last;

    const int tid  = threadIdx.x;
    const int lane = tid & 31;
    const int wid  = tid >> 5;                    // 0..3
    const int rowBase = blockIdx.x * 32;

    // zero accumulators + per-block dtype detection
    for (int d = tid; d < DDIM; d += 128) s_pacc[d] = 0.0f;
    {
        const float4 z = {0, 0, 0, 0};
        #pragma unroll
        for (int j = 0; j < 6; ++j) s_q[wid][lane + j * 32] = z;
    }
    if (tid == 0) s_flag = 0;
    __syncthreads();
    {
        // sample 64 int32 words at indices < NROWS (safe for i32 and i64).
        // i32 labels: 32 odd-indexed samples random in [0,10) -> all-zero
        // probability 1e-32. i64 LE small values: odd (high) words all zero.
        int base = rowBase;
        if (base > NROWS - 64) base = NROWS - 64;
        int w = ((const int*)labels)[base + (tid & 63)];
        if ((tid & 1) && w) atomicOr(&s_flag, 1);
    }
    __syncthreads();
    const bool isI64 = (s_flag == 0);
    const int entity_id = *entity_ptr;            // low 32 bits valid i32/i64

    // issue stage-s load into this warp's slot s&1 (empty group past end)
    auto issue = [&](int s) -> int {
        int lab = 0;
        if (s < NSTAGES) {
            const int row = rowBase + s * 4 + wid;
            lab = load_label(labels, row, isI64);     // uniform in warp
            if (lab != 0) {
                const float4* __restrict__ g =
                    (const float4*)(logits + (size_t)row * DDIM);
                float4* dst = &s_buf[wid][s & 1][0];
                #pragma unroll
                for (int j = 0; j < 6; ++j)
                    cp16(&dst[lane + j * 32], &g[lane + j * 32]);
            }
        }
        cp_commit();     // always: per-thread group count stays uniform
        return lab;
    };

    int labA = issue(0);
    int labB = issue(1);

    int nzLocal = 0, entLocal = 0;

    #pragma unroll 1
    for (int s = 0; s < NSTAGES; ++s) {
        cp_wait<1>();          // all groups but newest done -> slot resident
        __syncwarp();

        if (labA != 0) {
            const float4* __restrict__ r4 = &s_buf[wid][s & 1][0];
            const float4 v0 = r4[lane      ];
            const float4 v1 = r4[lane +  32];
            const float4 v2 = r4[lane +  64];
            const float4 v3 = r4[lane +  96];
            const float4 v4 = r4[lane + 128];
            const float4 v5 = r4[lane + 160];

            float nrm =
                v0.x*v0.x + v0.y*v0.y + v0.z*v0.z + v0.w*v0.w +
                v1.x*v1.x + v1.y*v1.y + v1.z*v1.z + v1.w*v1.w +
                v2.x*v2.x + v2.y*v2.y + v2.z*v2.z + v2.w*v2.w +
                v3.x*v3.x + v3.y*v3.y + v3.z*v3.z + v3.w*v3.w +
                v4.x*v4.x + v4.y*v4.y + v4.z*v4.z + v4.w*v4.w +
                v5.x*v5.x + v5.y*v5.y + v5.z*v5.z + v5.w*v5.w;
            #pragma unroll
            for (int off = 16; off > 0; off >>= 1)
                nrm += __shfl_xor_sync(0xFFFFFFFFu, nrm, off);
            const float rs = rsqrtf(nrm);    // ||row|| >> 0 for this data

            // q += v * rs  (warp-private smem, plain LDS/STS)
            #define QACC(J, V) { \
                float4 t = s_q[wid][lane + (J) * 32]; \
                t.x += (V).x * rs; t.y += (V).y * rs; \
                t.z += (V).z * rs; t.w += (V).w * rs; \
                s_q[wid][lane + (J) * 32] = t; }
            QACC(0, v0) QACC(1, v1) QACC(2, v2)
            QACC(3, v3) QACC(4, v4) QACC(5, v5)
            #undef QACC

            if (lane == 0) nzLocal++;

            const int row = rowBase + s * 4 + wid;
            if (labA == entity_id && (row & (SLEN - 1)) != 0) {
                if (lane == 0) entLocal++;
                // rare (~10% of rows): spread smem atomics
                #define PACC(J, V) \
                    atomicAdd(&s_pacc[(J)*128 + lane*4 + 0], (V).x); \
                    atomicAdd(&s_pacc[(J)*128 + lane*4 + 1], (V).y); \
                    atomicAdd(&s_pacc[(J)*128 + lane*4 + 2], (V).z); \
                    atomicAdd(&s_pacc[(J)*128 + lane*4 + 3], (V).w);
                PACC(0, v0) PACC(1, v1) PACC(2, v2)
                PACC(3, v3) PACC(4, v4) PACC(5, v5)
                #undef PACC
            }
        }
        __syncwarp();          // all lanes done reading this slot
        labA = labB;
        labB = issue(s + 2);   // refills the slot just vacated
    }

    // ---- block epilogue: flush partials to replicated global arrays ----
    if (lane == 0) { s_nz[wid] = nzLocal; s_ent[wid] = entLocal; }
    __syncthreads();

    const int rep  = blockIdx.x & (NREP - 1);
    const int entB = s_ent[0] + s_ent[1] + s_ent[2] + s_ent[3];
    {
        const float* qf = (const float*)s_q;      // [4][768]
        #pragma unroll
        for (int j = 0; j < 6; ++j) {
            const int d = j * 128 + tid;
            float qs = qf[d] + qf[DDIM + d] + qf[2*DDIM + d] + qf[3*DDIM + d];
            atomicAdd(&g_q8[rep][d], qs);
            if (entB) atomicAdd(&g_p8[rep][d], s_pacc[d]);
        }
    }
    if (tid == 0) {
        atomicAdd(&g_nzCount, s_nz[0] + s_nz[1] + s_nz[2] + s_nz[3]);
        if (entB) atomicAdd(&g_entCount, entB);
    }

    // ---- last block: final loss + state re-zero (no extra launch) ----
    __threadfence();
    if (tid == 0) {
        unsigned t = atomicAdd(&g_tk, 1u);
        s_last = (t == (unsigned)(NBLK - 1));
    }
    __syncthreads();
    if (!s_last) return;

    const float inv  = 1.0f / fmaxf((float)g_entCount, 1.0f);
    const float ntok = fmaxf((float)g_nzCount, 1.0f);
    float pp = 0.0f, qp = 0.0f;
    #pragma unroll
    for (int j = 0; j < 6; ++j) {
        const int d = j * 128 + tid;
        float ps = 0.0f, qs = 0.0f;
        #pragma unroll
        for (int r = 0; r < NREP; ++r) { ps += g_p8[r][d]; qs += g_q8[r][d]; }
        const float pd = ps * inv;
        pp += pd * pd;
        qp += qs * pd;
    }
    // tree reduce over 128 threads (reuse s_pacc)
    float* s_a = s_pacc;          // [0..127]
    float* s_b = s_pacc + 128;    // [128..255]
    s_a[tid] = pp;
    s_b[tid] = qp;
    __syncthreads();
    for (int off = 64; off > 0; off >>= 1) {
        if (tid < off) { s_a[tid] += s_a[tid + off]; s_b[tid] += s_b[tid + off]; }
        __syncthreads();
    }
    if (tid == 0) {
        const float pn = sqrtf(s_a[0]);
        d_out[0] = (pn > 0.0f) ? s_b[0] / (pn * ntok) : 0.0f;
        g_nzCount  = 0;
        g_entCount = 0;
        g_tk       = 0;
    }
    // re-zero replicas (reads above are complete: barriers passed)
    {
        float* pf = &g_p8[0][0];
        float* qf = &g_q8[0][0];
        for (int i = tid; i < NREP * DDIM; i += 128) { pf[i] = 0.0f; qf[i] = 0.0f; }
    }
}

extern "C" void kernel_launch(void* const* d_in, const int* in_sizes, int n_in,
                              void* d_out, int out_size) {
    const float* logits     = (const float*)d_in[0];
    const void*  labels     = d_in[1];
    const int*   entity_ptr = (const int*)d_in[2];
    (void)n_in; (void)in_sizes; (void)out_size;

    k_all<<<NBLK, 128>>>(logits, labels, entity_ptr, (float*)d_out);
}

// round 16
// speedup vs baseline: 1.3169x; 1.3169x over previous
#include <cuda_runtime.h>
#include <math.h>

#define DDIM  768
#define SLEN  512
#define NROWS 32768
#define EPSV  1e-8f

#define NBLK    1024             // x 128 thr, 32 rows/block
#define NSTAGES 8                // 32 rows / 4 warps
#define ROW_F4  (DDIM / 4)       // 192 float4 per row
#define NREP    8                // accumulator replicas (contention divider)
#define WARP_FLOATS (2 * ROW_F4 * 4)   // 1536 floats per warp region in s_buf

// ---- scratch (zero-initialized at load; last block restores zeros) ----
__device__ __align__(16) float g_p8[NREP][DDIM];   // proto partials
__device__ __align__(16) float g_q8[NREP][DDIM];   // q partials
__device__ int      g_entCount;
__device__ int      g_nzCount;
__device__ unsigned g_tk;                          // completion ticket

__device__ __forceinline__ int load_label(const void* __restrict__ labels,
                                          int r, bool isI64) {
    return isI64 ? (int)((const long long*)labels)[r]
                 : ((const int*)labels)[r];
}

__device__ __forceinline__ void cp16(float4* smem_dst, const float4* gsrc) {
    unsigned sa = (unsigned)__cvta_generic_to_shared(smem_dst);
    asm volatile("cp.async.cg.shared.global [%0], [%1], 16;\n"
                 :: "r"(sa), "l"(gsrc));
}
__device__ __forceinline__ void cp_commit() {
    asm volatile("cp.async.commit_group;\n" ::: "memory");
}
template <int N>
__device__ __forceinline__ void cp_wait() {
    asm volatile("cp.async.wait_group %0;\n" :: "n"(N) : "memory");
}

// ---------------------------------------------------------------------------
// ONE kernel. Algebra: loss = dot(q, proto) / (||proto|| * num_tok), with
//   q        = sum over rows with label!=0 of row/||row||      (no proto dep)
//   protoSum = sum over rows with label==entity && s!=0 of row
// Single 90MB pass; R10's barrier-free per-warp cp.async double buffer.
// q lives in 6 float4 REGISTER accumulators (the slots R10 used for proto).
// Epilogue parks q into the warp's OWN (dead) pipeline region at float base
// wid*WARP_FLOATS — R15's bug was parking at wid*768, which lands inside
// ANOTHER warp's live slot in this warp-major layout. protoSum via rare smem
// atomics. Per-block partials flush to NREP replicated global arrays
// (contention NBLK/NREP = 128 per address). Last block (ticket) computes the
// loss inline and re-zeros all device state for the next graph replay.
// ---------------------------------------------------------------------------
__global__ __launch_bounds__(128, 8)
void k_all(const float* __restrict__ logits,
           const void*  __restrict__ labels,
           const int*   __restrict__ entity_ptr,
           float* __restrict__ d_out) {
    __shared__ __align__(16) float4 s_buf[4][2][ROW_F4];   // pipeline, 24KB
    __shared__ float s_pacc[DDIM];                         // proto acc, 3KB
    __shared__ int   s_flag;
    __shared__ int   s_nz[4];
    __shared__ int   s_ent[4];
    __shared__ bool  s_last;

    const int tid  = threadIdx.x;
    const int lane = tid & 31;
    const int wid  = tid >> 5;                    // 0..3
    const int rowBase = blockIdx.x * 32;

    // zero proto accumulator + per-block dtype detection
    for (int d = tid; d < DDIM; d += 128) s_pacc[d] = 0.0f;
    if (tid == 0) s_flag = 0;
    __syncthreads();
    {
        // sample 64 int32 words at indices < NROWS (safe for i32 and i64).
        // i32 labels: 32 odd-indexed samples random in [0,10) -> all-zero
        // probability 1e-32. i64 LE small values: odd (high) words all zero.
        int base = rowBase;
        if (base > NROWS - 64) base = NROWS - 64;
        int w = ((const int*)labels)[base + (tid & 63)];
        if ((tid & 1) && w) atomicOr(&s_flag, 1);
    }
    __syncthreads();
    const bool isI64 = (s_flag == 0);
    const int entity_id = *entity_ptr;            // low 32 bits valid i32/i64

    // issue stage-s load into this warp's slot s&1 (empty group past end)
    auto issue = [&](int s) -> int {
        int lab = 0;
        if (s < NSTAGES) {
            const int row = rowBase + s * 4 + wid;
            lab = load_label(labels, row, isI64);     // uniform in warp
            if (lab != 0) {
                const float4* __restrict__ g =
                    (const float4*)(logits + (size_t)row * DDIM);
                float4* dst = &s_buf[wid][s & 1][0];
                #pragma unroll
                for (int j = 0; j < 6; ++j)
                    cp16(&dst[lane + j * 32], &g[lane + j * 32]);
            }
        }
        cp_commit();     // always: per-thread group count stays uniform
        return lab;
    };

    int labA = issue(0);
    int labB = issue(1);

    // q accumulator: this lane's 24-element row slice (register-resident)
    float4 q0 = {0,0,0,0}, q1 = q0, q2 = q0, q3 = q0, q4 = q0, q5 = q0;
    int nzLocal = 0, entLocal = 0;

    #pragma unroll 1
    for (int s = 0; s < NSTAGES; ++s) {
        cp_wait<1>();          // all groups but newest done -> slot resident
        __syncwarp();

        if (labA != 0) {
            const float4* __restrict__ r4 = &s_buf[wid][s & 1][0];
            const float4 v0 = r4[lane      ];
            const float4 v1 = r4[lane +  32];
            const float4 v2 = r4[lane +  64];
            const float4 v3 = r4[lane +  96];
            const float4 v4 = r4[lane + 128];
            const float4 v5 = r4[lane + 160];

            float nrm =
                v0.x*v0.x + v0.y*v0.y + v0.z*v0.z + v0.w*v0.w +
                v1.x*v1.x + v1.y*v1.y + v1.z*v1.z + v1.w*v1.w +
                v2.x*v2.x + v2.y*v2.y + v2.z*v2.z + v2.w*v2.w +
                v3.x*v3.x + v3.y*v3.y + v3.z*v3.z + v3.w*v3.w +
                v4.x*v4.x + v4.y*v4.y + v4.z*v4.z + v4.w*v4.w +
                v5.x*v5.x + v5.y*v5.y + v5.z*v5.z + v5.w*v5.w;
            #pragma unroll
            for (int off = 16; off > 0; off >>= 1)
                nrm += __shfl_xor_sync(0xFFFFFFFFu, nrm, off);
            const float rs = rsqrtf(nrm);    // ||row|| >> 0 for this data

            q0.x += v0.x*rs; q0.y += v0.y*rs; q0.z += v0.z*rs; q0.w += v0.w*rs;
            q1.x += v1.x*rs; q1.y += v1.y*rs; q1.z += v1.z*rs; q1.w += v1.w*rs;
            q2.x += v2.x*rs; q2.y += v2.y*rs; q2.z += v2.z*rs; q2.w += v2.w*rs;
            q3.x += v3.x*rs; q3.y += v3.y*rs; q3.z += v3.z*rs; q3.w += v3.w*rs;
            q4.x += v4.x*rs; q4.y += v4.y*rs; q4.z += v4.z*rs; q4.w += v4.w*rs;
            q5.x += v5.x*rs; q5.y += v5.y*rs; q5.z += v5.z*rs; q5.w += v5.w*rs;

            if (lane == 0) nzLocal++;

            const int row = rowBase + s * 4 + wid;
            if (labA == entity_id && (row & (SLEN - 1)) != 0) {
                if (lane == 0) entLocal++;
                // rare (~10% of rows): spread smem atomics
                #define PACC(J, V) \
                    atomicAdd(&s_pacc[(J)*128 + lane*4 + 0], (V).x); \
                    atomicAdd(&s_pacc[(J)*128 + lane*4 + 1], (V).y); \
                    atomicAdd(&s_pacc[(J)*128 + lane*4 + 2], (V).z); \
                    atomicAdd(&s_pacc[(J)*128 + lane*4 + 3], (V).w);
                PACC(0, v0) PACC(1, v1) PACC(2, v2)
                PACC(3, v3) PACC(4, v4) PACC(5, v5)
                #undef PACC
            }
        }
        __syncwarp();          // all lanes done reading this slot
        labA = labB;
        labB = issue(s + 2);   // refills the slot just vacated
    }

    // ---- block epilogue: park q regs in THIS WARP'S OWN dead pipeline
    //      region (float base wid*WARP_FLOATS; 1536 floats available, we
    //      write 768). Warp-private -> no pre-sync needed. ----
    {
        float* f = (float*)s_buf;
        const int b = wid * WARP_FLOATS + lane * 4;
        #define QST(J, V) \
            f[b + (J)*128 + 0] = (V).x; f[b + (J)*128 + 1] = (V).y; \
            f[b + (J)*128 + 2] = (V).z; f[b + (J)*128 + 3] = (V).w;
        QST(0, q0) QST(1, q1) QST(2, q2) QST(3, q3) QST(4, q4) QST(5, q5)
        #undef QST
    }
    if (lane == 0) { s_nz[wid] = nzLocal; s_ent[wid] = entLocal; }
    __syncthreads();

    const int rep  = blockIdx.x & (NREP - 1);
    const int entB = s_ent[0] + s_ent[1] + s_ent[2] + s_ent[3];
    {
        const float* qf = (const float*)s_buf;
        #pragma unroll
        for (int j = 0; j < 6; ++j) {
            const int d = j * 128 + tid;
            float qs = qf[0 * WARP_FLOATS + d] + qf[1 * WARP_FLOATS + d]
                     + qf[2 * WARP_FLOATS + d] + qf[3 * WARP_FLOATS + d];
            atomicAdd(&g_q8[rep][d], qs);
            if (entB) atomicAdd(&g_p8[rep][d], s_pacc[d]);
        }
    }
    if (tid == 0) {
        atomicAdd(&g_nzCount, s_nz[0] + s_nz[1] + s_nz[2] + s_nz[3]);
        if (entB) atomicAdd(&g_entCount, entB);
    }

    // ---- last block: final loss + state re-zero (no extra launch) ----
    __threadfence();
    if (tid == 0) {
        unsigned t = atomicAdd(&g_tk, 1u);
        s_last = (t == (unsigned)(NBLK - 1));
    }
    __syncthreads();
    if (!s_last) return;

    const float inv  = 1.0f / fmaxf((float)g_entCount, 1.0f);
    const float ntok = fmaxf((float)g_nzCount, 1.0f);
    float pp = 0.0f, qp = 0.0f;
    #pragma unroll
    for (int j = 0; j < 6; ++j) {
        const int d = j * 128 + tid;
        float ps = 0.0f, qs = 0.0f;
        #pragma unroll
        for (int r = 0; r < NREP; ++r) { ps += g_p8[r][d]; qs += g_q8[r][d]; }
        const float pd = ps * inv;
        pp += pd * pd;
        qp += qs * pd;
    }
    // tree reduce over 128 threads (reuse s_pacc)
    float* s_a = s_pacc;          // [0..127]
    float* s_b = s_pacc + 128;    // [128..255]
    s_a[tid] = pp;
    s_b[tid] = qp;
    __syncthreads();
    for (int off = 64; off > 0; off >>= 1) {
        if (tid < off) { s_a[tid] += s_a[tid + off]; s_b[tid] += s_b[tid + off]; }
        __syncthreads();
    }
    if (tid == 0) {
        const float pn = sqrtf(s_a[0]);
        d_out[0] = (pn > 0.0f) ? s_b[0] / (pn * ntok) : 0.0f;
        g_nzCount  = 0;
        g_entCount = 0;
        g_tk       = 0;
    }
    // re-zero replicas (reads above are complete: barriers passed)
    {
        float* pf = &g_p8[0][0];
        float* qf = &g_q8[0][0];
        for (int i = tid; i < NREP * DDIM; i += 128) { pf[i] = 0.0f; qf[i] = 0.0f; }
    }
}

extern "C" void kernel_launch(void* const* d_in, const int* in_sizes, int n_in,
                              void* d_out, int out_size) {
    const float* logits     = (const float*)d_in[0];
    const void*  labels     = d_in[1];
    const int*   entity_ptr = (const int*)d_in[2];
    (void)n_in; (void)in_sizes; (void)out_size;

    k_all<<<NBLK, 128>>>(logits, labels, entity_ptr, (float*)d_out);
}